// round 4
// baseline (speedup 1.0000x reference)
#include <cuda_runtime.h>

#define NN 100000
#define INC 128
#define HID 64
#define OUTC 32

// Scratch (device globals — no allocation allowed in kernel_launch)
__device__ float g_deg[NN];            // deg, then dinv in-place
__device__ float g_h1[NN * HID];       // x @ W1
__device__ float g_o1[NN * HID];       // aggregated layer-1 output (pre-relu)
__device__ float g_h2[NN * OUTC];      // relu(o1) @ W2

// ---------------------------------------------------------------------------
// degree / normalization
// ---------------------------------------------------------------------------
__global__ void k_deg_init(float* __restrict__ deg, int n) {
    int i = blockIdx.x * blockDim.x + threadIdx.x;
    if (i < n) deg[i] = 1.0f;   // self loop
}

__global__ void k_deg_edge(const int* __restrict__ dst,
                           float* __restrict__ deg, int E) {
    int i = blockIdx.x * blockDim.x + threadIdx.x;
    if (i < E) atomicAdd(&deg[dst[i]], 1.0f);
}

__global__ void k_dinv(float* __restrict__ deg, int n) {
    int i = blockIdx.x * blockDim.x + threadIdx.x;
    if (i < n) deg[i] = rsqrtf(deg[i]);
}

// ---------------------------------------------------------------------------
// Tiled fp32 GEMM: H[M,N] = op(X)[M,K] @ W[K,N], op = optional relu on X load.
// ---------------------------------------------------------------------------
template <int K, int N, int TM, int KT, bool RELU>
__global__ __launch_bounds__(256) void k_gemm(const float* __restrict__ X,
                                              const float* __restrict__ W,
                                              float* __restrict__ H, int M) {
    constexpr int CT  = N / 4;       // threads along N (4 cols each)
    constexpr int RT  = 256 / CT;    // threads along M
    constexpr int RPT = TM / RT;     // rows per thread
    constexpr int TMP = TM + 1;      // padded stride for transposed X tile

    __shared__ float Ws[KT * N];
    __shared__ float Xs[KT * TMP];

    const int t    = threadIdx.x;
    const int row0 = blockIdx.x * TM;
    const int ct   = t % CT;
    const int rt   = t / CT;

    float acc[RPT][4];
#pragma unroll
    for (int r = 0; r < RPT; r++) {
        acc[r][0] = 0.f; acc[r][1] = 0.f; acc[r][2] = 0.f; acc[r][3] = 0.f;
    }

    for (int k0 = 0; k0 < K; k0 += KT) {
        __syncthreads();
        for (int i = t * 4; i < KT * N; i += 1024) {
            *(float4*)&Ws[i] = *(const float4*)&W[k0 * N + i];
        }
        for (int i = t * 4; i < TM * KT; i += 1024) {
            int r  = i / KT;
            int c  = i % KT;
            int gr = row0 + r;
            float4 v = make_float4(0.f, 0.f, 0.f, 0.f);
            if (gr < M) v = *(const float4*)&X[gr * K + k0 + c];
            if (RELU) {
                v.x = fmaxf(v.x, 0.f); v.y = fmaxf(v.y, 0.f);
                v.z = fmaxf(v.z, 0.f); v.w = fmaxf(v.w, 0.f);
            }
            Xs[(c + 0) * TMP + r] = v.x;
            Xs[(c + 1) * TMP + r] = v.y;
            Xs[(c + 2) * TMP + r] = v.z;
            Xs[(c + 3) * TMP + r] = v.w;
        }
        __syncthreads();

#pragma unroll 8
        for (int kk = 0; kk < KT; kk++) {
            float4 w = *(const float4*)&Ws[kk * N + ct * 4];
#pragma unroll
            for (int r = 0; r < RPT; r++) {
                float xv = Xs[kk * TMP + rt * RPT + r];
                acc[r][0] = fmaf(xv, w.x, acc[r][0]);
                acc[r][1] = fmaf(xv, w.y, acc[r][1]);
                acc[r][2] = fmaf(xv, w.z, acc[r][2]);
                acc[r][3] = fmaf(xv, w.w, acc[r][3]);
            }
        }
    }

#pragma unroll
    for (int r = 0; r < RPT; r++) {
        int gr = row0 + rt * RPT + r;
        if (gr < M) {
            float4 o = make_float4(acc[r][0], acc[r][1], acc[r][2], acc[r][3]);
            *(float4*)&H[gr * N + ct * 4] = o;
        }
    }
}

// ---------------------------------------------------------------------------
// out[i] = b + dinv[i]^2 * h[i]  (self loop + bias; initializes every element)
// ---------------------------------------------------------------------------
template <int C>
__global__ void k_self(const float* __restrict__ h, const float* __restrict__ dinv,
                       const float* __restrict__ b, float* __restrict__ out, int M) {
    constexpr int Q = C / 4;
    int idx = blockIdx.x * blockDim.x + threadIdx.x;
    if (idx >= M * Q) return;
    int i = idx / Q, q = idx % Q;
    float s = dinv[i];
    s *= s;
    float4 v  = *(const float4*)&h[i * C + q * 4];
    float4 bb = *(const float4*)&b[q * 4];
    float4 o  = make_float4(fmaf(s, v.x, bb.x), fmaf(s, v.y, bb.y),
                            fmaf(s, v.z, bb.z), fmaf(s, v.w, bb.w));
    *(float4*)&out[i * C + q * 4] = o;
}

// ---------------------------------------------------------------------------
// Edge scatter: out[dst] += dinv[src]*dinv[dst] * h[src]  (scalar RED adds)
// One thread handles 4 consecutive channels of one edge.
// ---------------------------------------------------------------------------
template <int C>
__global__ void k_edge(const float* __restrict__ h,
                       const int* __restrict__ src,
                       const int* __restrict__ dst,
                       const float* __restrict__ dinv,
                       float* __restrict__ out, int E) {
    constexpr int Q = C / 4;
    int idx = blockIdx.x * blockDim.x + threadIdx.x;
    if (idx >= E * Q) return;
    int e = idx / Q, q = idx % Q;
    int s = src[e];
    int d = dst[e];
    float nrm = dinv[s] * dinv[d];
    float4 v = *(const float4*)&h[s * C + q * 4];
    float* p = &out[d * C + q * 4];
    atomicAdd(p + 0, nrm * v.x);
    atomicAdd(p + 1, nrm * v.y);
    atomicAdd(p + 2, nrm * v.z);
    atomicAdd(p + 3, nrm * v.w);
}

// ---------------------------------------------------------------------------
extern "C" void kernel_launch(void* const* d_in, const int* in_sizes, int n_in,
                              void* d_out, int out_size) {
    const float* x   = (const float*)d_in[0];
    const int*   ei  = (const int*)d_in[1];     // int32! (jax x64 disabled)
    const float* W1  = (const float*)d_in[2];
    const float* b1  = (const float*)d_in[3];
    const float* W2  = (const float*)d_in[4];
    const float* b2  = (const float*)d_in[5];
    float*       out = (float*)d_out;

    const int M = in_sizes[0] / INC;       // 100000
    const int E = in_sizes[1] / 2;         // 1600000
    const int* src = ei;
    const int* dst = ei + E;

    float *deg = nullptr, *h1 = nullptr, *o1 = nullptr, *h2 = nullptr;
    cudaGetSymbolAddress((void**)&deg, g_deg);
    cudaGetSymbolAddress((void**)&h1,  g_h1);
    cudaGetSymbolAddress((void**)&o1,  g_o1);
    cudaGetSymbolAddress((void**)&h2,  g_h2);

    const int B = 256;

    // normalization
    k_deg_init<<<(M + B - 1) / B, B>>>(deg, M);
    k_deg_edge<<<(E + B - 1) / B, B>>>(dst, deg, E);
    k_dinv<<<(M + B - 1) / B, B>>>(deg, M);

    // layer 1: h1 = x @ W1
    k_gemm<INC, HID, 64, 64, false><<<(M + 63) / 64, 256>>>(x, W1, h1, M);
    k_self<HID><<<(M * (HID / 4) + B - 1) / B, B>>>(h1, deg, b1, o1, M);
    k_edge<HID><<<(E * (HID / 4) + B - 1) / B, B>>>(h1, src, dst, deg, o1, E);

    // layer 2: h2 = relu(o1) @ W2
    k_gemm<HID, OUTC, 64, 64, true><<<(M + 63) / 64, 256>>>(o1, W2, h2, M);
    k_self<OUTC><<<(M * (OUTC / 4) + B - 1) / B, B>>>(h2, deg, b2, out, M);
    k_edge<OUTC><<<(E * (OUTC / 4) + B - 1) / B, B>>>(h2, src, dst, deg, out, E);
}

// round 5
// speedup vs baseline: 1.1131x; 1.1131x over previous
#include <cuda_runtime.h>

#define NN   100000
#define EMAX 1600000
#define INC  128
#define HID  64
#define OUTC 32

// Scratch (device globals — no allocation allowed in kernel_launch)
__device__ float g_dinv[NN];
__device__ int   g_cnt[NN];
__device__ int   g_off[NN + 1];
__device__ int   g_cur[NN];
__device__ int   g_srcn[EMAX];        // CSR-permuted source indices (by dst)
__device__ float g_nrm[EMAX];         // per-edge norm dinv[s]*dinv[d]
__device__ float g_h1[NN * HID];      // x @ W1
__device__ float g_o1[NN * HID];      // aggregated layer-1 output (pre-relu)
__device__ float g_h2[NN * OUTC];     // relu(o1) @ W2

// ---------------------------------------------------------------------------
// degree count (int atomics)
// ---------------------------------------------------------------------------
__global__ void k_cnt_init(int* __restrict__ cnt, int n) {
    int i = blockIdx.x * blockDim.x + threadIdx.x;
    if (i < n) cnt[i] = 0;
}

__global__ void k_cnt_edge(const int* __restrict__ dst, int* __restrict__ cnt, int E) {
    int i = blockIdx.x * blockDim.x + threadIdx.x;
    if (i < E) atomicAdd(&cnt[dst[i]], 1);
}

// ---------------------------------------------------------------------------
// Single-block exclusive scan over cnt -> off/cur; also dinv = rsqrt(cnt+1).
// 1024 threads, contiguous chunks, Hillis-Steele block scan of partials.
// ---------------------------------------------------------------------------
__global__ __launch_bounds__(1024) void k_scan(const int* __restrict__ cnt,
                                               int* __restrict__ off,
                                               int* __restrict__ cur,
                                               float* __restrict__ dinv, int n) {
    __shared__ int sums[1024];
    const int t = threadIdx.x;
    const int chunk = (n + 1023) / 1024;
    const int lo = t * chunk;
    const int hi = min(lo + chunk, n);

    int s = 0;
    for (int i = lo; i < hi; i++) s += cnt[i];
    sums[t] = s;
    __syncthreads();

    for (int ofs = 1; ofs < 1024; ofs <<= 1) {
        int add = (t >= ofs) ? sums[t - ofs] : 0;
        __syncthreads();
        sums[t] += add;
        __syncthreads();
    }

    int run = sums[t] - s;     // exclusive prefix for this chunk
    for (int i = lo; i < hi; i++) {
        off[i] = run;
        cur[i] = run;
        int c = cnt[i];
        run += c;
        dinv[i] = rsqrtf((float)c + 1.0f);   // +1 self loop
    }
    if (t == 1023) off[n] = sums[1023];      // total = E
}

// ---------------------------------------------------------------------------
// CSR build: permute edges into dst-bucketed lists, precompute norms.
// ---------------------------------------------------------------------------
__global__ void k_build(const int* __restrict__ src, const int* __restrict__ dst,
                        const float* __restrict__ dinv, int* __restrict__ cur,
                        int* __restrict__ srcn, float* __restrict__ nrm, int E) {
    int e = blockIdx.x * blockDim.x + threadIdx.x;
    if (e >= E) return;
    int s = src[e];
    int d = dst[e];
    int pos = atomicAdd(&cur[d], 1);
    srcn[pos] = s;
    nrm[pos]  = dinv[s] * dinv[d];
}

// ---------------------------------------------------------------------------
// Tiled fp32 GEMM: H[M,N] = op(X)[M,K] @ W[K,N], op = optional relu on X load.
// ---------------------------------------------------------------------------
template <int K, int N, int TM, int KT, bool RELU>
__global__ __launch_bounds__(256) void k_gemm(const float* __restrict__ X,
                                              const float* __restrict__ W,
                                              float* __restrict__ H, int M) {
    constexpr int CT  = N / 4;
    constexpr int RT  = 256 / CT;
    constexpr int RPT = TM / RT;
    constexpr int TMP = TM + 1;

    __shared__ float Ws[KT * N];
    __shared__ float Xs[KT * TMP];

    const int t    = threadIdx.x;
    const int row0 = blockIdx.x * TM;
    const int ct   = t % CT;
    const int rt   = t / CT;

    float acc[RPT][4];
#pragma unroll
    for (int r = 0; r < RPT; r++) {
        acc[r][0] = 0.f; acc[r][1] = 0.f; acc[r][2] = 0.f; acc[r][3] = 0.f;
    }

    for (int k0 = 0; k0 < K; k0 += KT) {
        __syncthreads();
        for (int i = t * 4; i < KT * N; i += 1024) {
            *(float4*)&Ws[i] = *(const float4*)&W[k0 * N + i];
        }
        for (int i = t * 4; i < TM * KT; i += 1024) {
            int r  = i / KT;
            int c  = i % KT;
            int gr = row0 + r;
            float4 v = make_float4(0.f, 0.f, 0.f, 0.f);
            if (gr < M) v = *(const float4*)&X[gr * K + k0 + c];
            if (RELU) {
                v.x = fmaxf(v.x, 0.f); v.y = fmaxf(v.y, 0.f);
                v.z = fmaxf(v.z, 0.f); v.w = fmaxf(v.w, 0.f);
            }
            Xs[(c + 0) * TMP + r] = v.x;
            Xs[(c + 1) * TMP + r] = v.y;
            Xs[(c + 2) * TMP + r] = v.z;
            Xs[(c + 3) * TMP + r] = v.w;
        }
        __syncthreads();

#pragma unroll 8
        for (int kk = 0; kk < KT; kk++) {
            float4 w = *(const float4*)&Ws[kk * N + ct * 4];
#pragma unroll
            for (int r = 0; r < RPT; r++) {
                float xv = Xs[kk * TMP + rt * RPT + r];
                acc[r][0] = fmaf(xv, w.x, acc[r][0]);
                acc[r][1] = fmaf(xv, w.y, acc[r][1]);
                acc[r][2] = fmaf(xv, w.z, acc[r][2]);
                acc[r][3] = fmaf(xv, w.w, acc[r][3]);
            }
        }
    }

#pragma unroll
    for (int r = 0; r < RPT; r++) {
        int gr = row0 + rt * RPT + r;
        if (gr < M) {
            float4 o = make_float4(acc[r][0], acc[r][1], acc[r][2], acc[r][3]);
            *(float4*)&H[gr * N + ct * 4] = o;
        }
    }
}

// ---------------------------------------------------------------------------
// Gather aggregation: C/4-thread group per node.
// out[i] = b + dinv[i]^2*h[i] + sum_j nrm[j]*h[srcn[j]]   (registers only)
// ---------------------------------------------------------------------------
template <int C>
__global__ __launch_bounds__(256) void k_gather(const float* __restrict__ h,
                                                const int* __restrict__ off,
                                                const int* __restrict__ srcn,
                                                const float* __restrict__ nrm,
                                                const float* __restrict__ dinv,
                                                const float* __restrict__ b,
                                                float* __restrict__ out, int M) {
    constexpr int Q = C / 4;          // threads per node
    constexpr int G = 256 / Q;        // nodes per block
    const int q = threadIdx.x % Q;
    const int g = threadIdx.x / Q;
    const int i = blockIdx.x * G + g;
    if (i >= M) return;

    const float di = dinv[i];
    const float s2 = di * di;
    float4 bb = *(const float4*)&b[q * 4];
    float4 v  = *(const float4*)&h[i * C + q * 4];
    float4 acc = make_float4(fmaf(s2, v.x, bb.x), fmaf(s2, v.y, bb.y),
                             fmaf(s2, v.z, bb.z), fmaf(s2, v.w, bb.w));

    int j  = off[i];
    const int j1 = off[i + 1];

    // software-pipelined x2 for memory-level parallelism
    for (; j + 1 < j1; j += 2) {
        int   sA = __ldg(&srcn[j]);
        int   sB = __ldg(&srcn[j + 1]);
        float wA = __ldg(&nrm[j]);
        float wB = __ldg(&nrm[j + 1]);
        float4 uA = *(const float4*)&h[sA * C + q * 4];
        float4 uB = *(const float4*)&h[sB * C + q * 4];
        acc.x = fmaf(wA, uA.x, acc.x); acc.y = fmaf(wA, uA.y, acc.y);
        acc.z = fmaf(wA, uA.z, acc.z); acc.w = fmaf(wA, uA.w, acc.w);
        acc.x = fmaf(wB, uB.x, acc.x); acc.y = fmaf(wB, uB.y, acc.y);
        acc.z = fmaf(wB, uB.z, acc.z); acc.w = fmaf(wB, uB.w, acc.w);
    }
    if (j < j1) {
        int   s = __ldg(&srcn[j]);
        float w = __ldg(&nrm[j]);
        float4 u = *(const float4*)&h[s * C + q * 4];
        acc.x = fmaf(w, u.x, acc.x); acc.y = fmaf(w, u.y, acc.y);
        acc.z = fmaf(w, u.z, acc.z); acc.w = fmaf(w, u.w, acc.w);
    }

    *(float4*)&out[i * C + q * 4] = acc;
}

// ---------------------------------------------------------------------------
extern "C" void kernel_launch(void* const* d_in, const int* in_sizes, int n_in,
                              void* d_out, int out_size) {
    const float* x   = (const float*)d_in[0];
    const int*   ei  = (const int*)d_in[1];     // int32 (jax x64 disabled)
    const float* W1  = (const float*)d_in[2];
    const float* b1  = (const float*)d_in[3];
    const float* W2  = (const float*)d_in[4];
    const float* b2  = (const float*)d_in[5];
    float*       out = (float*)d_out;

    const int M = in_sizes[0] / INC;       // 100000
    const int E = in_sizes[1] / 2;         // 1600000
    const int* src = ei;
    const int* dst = ei + E;

    float *dinv, *h1, *o1, *h2, *nrm;
    int *cnt, *off, *cur, *srcn;
    cudaGetSymbolAddress((void**)&dinv, g_dinv);
    cudaGetSymbolAddress((void**)&cnt,  g_cnt);
    cudaGetSymbolAddress((void**)&off,  g_off);
    cudaGetSymbolAddress((void**)&cur,  g_cur);
    cudaGetSymbolAddress((void**)&srcn, g_srcn);
    cudaGetSymbolAddress((void**)&nrm,  g_nrm);
    cudaGetSymbolAddress((void**)&h1,   g_h1);
    cudaGetSymbolAddress((void**)&o1,   g_o1);
    cudaGetSymbolAddress((void**)&h2,   g_h2);

    const int B = 256;

    // CSR build + normalization
    k_cnt_init<<<(M + B - 1) / B, B>>>(cnt, M);
    k_cnt_edge<<<(E + B - 1) / B, B>>>(dst, cnt, E);
    k_scan<<<1, 1024>>>(cnt, off, cur, dinv, M);
    k_build<<<(E + B - 1) / B, B>>>(src, dst, dinv, cur, srcn, nrm, E);

    // layer 1: h1 = x @ W1 ; o1 = gather(h1)
    k_gemm<INC, HID, 64, 64, false><<<(M + 63) / 64, 256>>>(x, W1, h1, M);
    k_gather<HID><<<(M * (HID / 4) + B - 1) / B, B>>>(h1, off, srcn, nrm, dinv, b1, o1, M);

    // layer 2: h2 = relu(o1) @ W2 ; out = gather(h2)
    k_gemm<HID, OUTC, 64, 64, true><<<(M + 63) / 64, 256>>>(o1, W2, h2, M);
    k_gather<OUTC><<<(M * (OUTC / 4) + B - 1) / B, B>>>(h2, off, srcn, nrm, dinv, b2, out, M);
}